// round 13
// baseline (speedup 1.0000x reference)
#include <cuda_runtime.h>
#include <cuda_bf16.h>
#include <cstdint>

#define BATCH 2
#define NN    4096
#define CINN  128
#define CC    64
#define TOTROWS (BATCH * NN)       // 8192
#define HOUT_ELEMS (TOTROWS * CC)  // 524288

// ---------------- scratch (device globals; no allocation allowed) ----------
__device__ float g_u[TOTROWS];
__device__ float g_v[TOTROWS];
__device__ float g_invS[TOTROWS];
__device__ __nv_bfloat16 g_hTbh[BATCH * CC * NN];  // [b][c][n] hi
__device__ __nv_bfloat16 g_hTbl[BATCH * CC * NN];  // [b][c][n] lo residual

__device__ __forceinline__ float sigmoidf(float x) {
    return __fdividef(1.0f, 1.0f + __expf(-x));
}
__device__ __forceinline__ uint32_t smem_u32(const void* p) {
    uint32_t a;
    asm("{ .reg .u64 t; cvta.to.shared.u64 t, %1; cvt.u32.u64 %0, t; }" : "=r"(a) : "l"(p));
    return a;
}
#define SWZ(x) ((x) ^ (((x) >> 3) & 0x70))

#define BAR_SYNC(id)   asm volatile("bar.sync %0, 256;"   :: "r"(id) : "memory")
#define BAR_ARRIVE(id) asm volatile("bar.arrive %0, 256;" :: "r"(id) : "memory")

// split two floats into packed bf16x2 hi + lo-residual (low half = first elem)
__device__ __forceinline__ void split2(float a, float b, uint32_t& hi, uint32_t& lo) {
    __nv_bfloat16 ah = __float2bfloat16(a), bh = __float2bfloat16(b);
    float ar = a - __bfloat162float(ah);
    float br = b - __bfloat162float(bh);
    __nv_bfloat16 al = __float2bfloat16(ar), bl = __float2bfloat16(br);
    hi = ((uint32_t)__bfloat16_as_ushort(bh) << 16) | __bfloat16_as_ushort(ah);
    lo = ((uint32_t)__bfloat16_as_ushort(bl) << 16) | __bfloat16_as_ushort(al);
}

#define LDSM4(r0, r1, r2, r3, addr)                                            \
    asm volatile("ldmatrix.sync.aligned.m8n8.x4.shared.b16 {%0,%1,%2,%3}, [%4];" \
                 : "=r"(r0), "=r"(r1), "=r"(r2), "=r"(r3) : "r"(addr))

#define MMA16816(c, a0, a1, a2, a3, b0, b1)                                    \
    asm volatile("mma.sync.aligned.m16n8k16.row.col.f32.bf16.bf16.f32 "        \
                 "{%0,%1,%2,%3}, {%4,%5,%6,%7}, {%8,%9}, {%0,%1,%2,%3};"       \
                 : "+f"((c)[0]), "+f"((c)[1]), "+f"((c)[2]), "+f"((c)[3])      \
                 : "r"(a0), "r"(a1), "r"(a2), "r"(a3), "r"(b0), "r"(b1))

// ===========================================================================
// Kernel 1: h = relu(relu(x@W1+b1)@W2+b2); u, v; h^T -> bf16 hi/lo
// ===========================================================================
extern __shared__ float s1[];

__global__ void k1_mlp(const float* __restrict__ x,
                       const float* __restrict__ W1,
                       const float* __restrict__ b1,
                       const float* __restrict__ W2,
                       const float* __restrict__ b2,
                       const float* __restrict__ Wa)
{
    float* sW1 = s1;             // 8192
    float* sW2 = sW1 + 8192;     // 4096
    float* sWa = sW2 + 4096;     // 128
    float* sX  = sWa + 128;      // 4096 (reused as sH2)
    float* sH1 = sX + 4096;      // 2048

    const int t = threadIdx.x;
    const int grow0 = blockIdx.x * 32;

    {
        const float4* W1v = (const float4*)W1;
        float4* d = (float4*)sW1;
        #pragma unroll
        for (int p = t; p < 2048; p += 256) d[p] = W1v[p];
        const float4* W2v = (const float4*)W2;
        float4* d2 = (float4*)sW2;
        #pragma unroll
        for (int p = t; p < 1024; p += 256) d2[p] = W2v[p];
        if (t < 32) ((float4*)sWa)[t] = ((const float4*)Wa)[t];
        const float4* Xv = (const float4*)(x + (long)grow0 * CINN);
        float4* dx = (float4*)sX;
        #pragma unroll
        for (int p = t; p < 1024; p += 256) dx[p] = Xv[p];
    }
    __syncthreads();

    const int ch = t & 63;
    const int rg = t >> 6;
    const float bb1 = b1[ch];
    const float bb2 = b2[ch];

    float acc[8];
    #pragma unroll
    for (int k = 0; k < 8; k++) acc[k] = bb1;

    #pragma unroll 4
    for (int i = 0; i < CINN; i += 4) {
        float w0 = sW1[(i + 0) * 64 + ch];
        float w1 = sW1[(i + 1) * 64 + ch];
        float w2 = sW1[(i + 2) * 64 + ch];
        float w3 = sW1[(i + 3) * 64 + ch];
        #pragma unroll
        for (int k = 0; k < 8; k++) {
            const float4 x4 = *(const float4*)(sX + (rg + 4 * k) * CINN + i);
            acc[k] = fmaf(x4.x, w0, acc[k]);
            acc[k] = fmaf(x4.y, w1, acc[k]);
            acc[k] = fmaf(x4.z, w2, acc[k]);
            acc[k] = fmaf(x4.w, w3, acc[k]);
        }
    }
    #pragma unroll
    for (int k = 0; k < 8; k++)
        sH1[(rg + 4 * k) * 64 + ch] = fmaxf(acc[k], 0.0f);
    __syncthreads();

    #pragma unroll
    for (int k = 0; k < 8; k++) acc[k] = bb2;

    #pragma unroll 4
    for (int i = 0; i < CC; i += 4) {
        float w0 = sW2[(i + 0) * 64 + ch];
        float w1 = sW2[(i + 1) * 64 + ch];
        float w2 = sW2[(i + 2) * 64 + ch];
        float w3 = sW2[(i + 3) * 64 + ch];
        #pragma unroll
        for (int k = 0; k < 8; k++) {
            const float4 h4 = *(const float4*)(sH1 + (rg + 4 * k) * 64 + i);
            acc[k] = fmaf(h4.x, w0, acc[k]);
            acc[k] = fmaf(h4.y, w1, acc[k]);
            acc[k] = fmaf(h4.z, w2, acc[k]);
            acc[k] = fmaf(h4.w, w3, acc[k]);
        }
    }

    float* sH2 = sX;
    #pragma unroll
    for (int k = 0; k < 8; k++) {
        const int r = rg + 4 * k;
        sH2[r * 64 + ch] = fmaxf(acc[k], 0.0f);
    }
    __syncthreads();

    // h^T bf16 hi/lo: thread t -> channel t>>2, nodes (t&3)*8 .. +7
    {
        const int b = grow0 >> 12;
        const int nloc0 = (grow0 & (NN - 1));   // batch-local node base
        const int ch2 = t >> 2;
        const int n0 = (t & 3) * 8;
        uint32_t hp[4], lp[4];
        #pragma unroll
        for (int q = 0; q < 4; q++) {
            const float e0 = sH2[(n0 + 2 * q + 0) * 64 + ch2];
            const float e1 = sH2[(n0 + 2 * q + 1) * 64 + ch2];
            split2(e0, e1, hp[q], lp[q]);
        }
        const long gi = (long)(b * CC + ch2) * NN + nloc0 + n0;
        *(uint4*)((char*)g_hTbh + gi * 2) = *(uint4*)hp;
        *(uint4*)((char*)g_hTbl + gi * 2) = *(uint4*)lp;
    }

    const int w = t >> 5, lane = t & 31;
    for (int rr = w * 4; rr < w * 4 + 4; rr++) {
        const float a0 = sH2[rr * 64 + lane];
        const float a1 = sH2[rr * 64 + lane + 32];
        float up = a0 * sWa[lane]      + a1 * sWa[lane + 32];
        float vp = a0 * sWa[64 + lane] + a1 * sWa[96 + lane];
        #pragma unroll
        for (int off = 16; off > 0; off >>= 1) {
            up += __shfl_down_sync(0xffffffffu, up, off);
            vp += __shfl_down_sync(0xffffffffu, vp, off);
        }
        if (lane == 0) { g_u[grow0 + rr] = up; g_v[grow0 + rr] = vp; }
    }
}

// ===========================================================================
// Kernel A: row sums only -> g_invS
// ===========================================================================
__global__ void kA_rowsum(const float* __restrict__ adj,
                          const float* __restrict__ ba)
{
    __shared__ __align__(16) float sV[NN];
    __shared__ float sRed[8];

    const int t = threadIdx.x;
    const int grow0 = blockIdx.x * 4;
    const int b = grow0 >> 12;

    {
        const float4* vv = (const float4*)(g_v + (long)b * NN);
        float4* d = (float4*)sV;
        #pragma unroll
        for (int p = t; p < 1024; p += 256) d[p] = vv[p];
    }
    __syncthreads();

    const int rg = t >> 6, l64 = t & 63;
    const int grow = grow0 + rg;
    const float u = g_u[grow] + ba[0];
    const float4* ar = (const float4*)(adj + (long)grow * NN);

    float s = 0.0f;
    #pragma unroll 4
    for (int it = 0; it < 16; it++) {
        const int f = l64 + 64 * it;
        const float4 a4 = __ldcs(ar + f);
        const int j = f * 4;
        s += a4.x * sigmoidf(u + sV[j + 0]);
        s += a4.y * sigmoidf(u + sV[j + 1]);
        s += a4.z * sigmoidf(u + sV[j + 2]);
        s += a4.w * sigmoidf(u + sV[j + 3]);
    }
    #pragma unroll
    for (int off = 16; off > 0; off >>= 1)
        s += __shfl_down_sync(0xffffffffu, s, off);
    const int w = t >> 5, lane = t & 31;
    if (lane == 0) sRed[w] = s;
    __syncthreads();
    if (t < 4) {
        const float S = sRed[2 * t] + sRed[2 * t + 1];
        g_invS[grow0 + t] = 1.0f / (S + 1e-10f);
    }
}

// ===========================================================================
// Kernel B (warp-specialized, occupancy 2): MB=32 rows/CTA, grid 256,
// 256 thr (4 producer + 4 consumer warps). 2 CTAs/SM fill pipeline bubbles
// and all 148 SMs get work. Named barriers: FULL(s)=1+s, EMPTY(s)=3+s.
// ===========================================================================
#define MB 32
#define JC 64
#define NCH (NN / JC)
#define STG 24576   // Ah 4K | Al 4K | Bh 8K | Bl 8K

__global__ void __launch_bounds__(256, 2)
kB_fused(const float* __restrict__ adj,
         const float* __restrict__ ba,
         float* __restrict__ out_h,
         float* __restrict__ out_a)
{
    extern __shared__ char dsm[];
    __shared__ __align__(16) float sV[NN];

    char* tiles = (char*)(((uintptr_t)dsm + 1023) & ~(uintptr_t)1023);
    const uint32_t tiles_u32 = smem_u32(tiles);

    const int t = threadIdx.x;
    const int lane = t & 31;
    const int grow0 = blockIdx.x * MB;
    const int b = grow0 >> 12;

    {
        const float4* vv = (const float4*)(g_v + (long)b * NN);
        float4* d = (float4*)sV;
        #pragma unroll
        for (int p = t; p < 1024; p += 256) d[p] = vv[p];
    }
    __syncthreads();   // sV visible; ONLY use of barrier 0

    if (t < 128) {
        // ==================== PRODUCER (4 warps) ====================
        const float bav = ba[0];
        const int rbase = t >> 4;       // 0..7 -> rows rbase+8i (i=0..3)
        const int f4 = t & 15;
        float ru[4], rinv[4];
        #pragma unroll
        for (int i = 0; i < 4; i++) {
            ru[i]   = g_u[grow0 + rbase + 8 * i] + bav;
            rinv[i] = g_invS[grow0 + rbase + 8 * i];
        }
        // B staging: slots t+128k (k=0..3): brow = (t>>3)+16k, bc = t&7
        const int brb = t >> 3;          // 0..15
        const int bc = t & 7;
        const char* hTh[4];
        const char* hTl[4];
        #pragma unroll
        for (int k = 0; k < 4; k++) {
            const int brow = brb + 16 * k;
            hTh[k] = (const char*)(g_hTbh + (long)(b * CC + brow) * NN);
            hTl[k] = (const char*)(g_hTbl + (long)(b * CC + brow) * NN);
        }

        float4 pa[4];
        uint4 pBh[4], pBl[4];

        // prologue: LDG chunk 0
        #pragma unroll
        for (int i = 0; i < 4; i++)
            pa[i] = __ldcs((const float4*)(adj + (long)(grow0 + rbase + 8 * i) * NN) + f4);
        #pragma unroll
        for (int k = 0; k < 4; k++) {
            pBh[k] = *(const uint4*)(hTh[k] + (long)(bc * 8) * 2);
            pBl[k] = *(const uint4*)(hTl[k] + (long)(bc * 8) * 2);
        }

        for (int c = 0; c < NCH; c++) {
            const int j0 = c * JC;
            const int s = c & 1;
            char* Ah = tiles + s * STG;
            char* Al = Ah + 4096;
            char* Bh = Ah + 8192;
            char* Bl = Ah + 16384;

            if (c >= 2) BAR_SYNC(3 + s);   // wait consumers freed stage s

            // compute e + commit
            const int jj = f4 * 4;
            #pragma unroll
            for (int i = 0; i < 4; i++) {
                const int row = rbase + 8 * i;
                const float u = ru[i], inv = rinv[i];
                const float4 a4 = pa[i];
                float4 o;
                o.x = a4.x * sigmoidf(u + sV[j0 + jj + 0]) * inv;
                o.y = a4.y * sigmoidf(u + sV[j0 + jj + 1]) * inv;
                o.z = a4.z * sigmoidf(u + sV[j0 + jj + 2]) * inv;
                o.w = a4.w * sigmoidf(u + sV[j0 + jj + 3]) * inv;
                __stcs((float4*)(out_a + (long)(grow0 + row) * NN + j0) + f4, o);
                uint2 hv, lv;
                split2(o.x, o.y, hv.x, lv.x);
                split2(o.z, o.w, hv.y, lv.y);
                const uint32_t off = SWZ((uint32_t)(row * 128 + f4 * 8));
                *(uint2*)(Ah + off) = hv;
                *(uint2*)(Al + off) = lv;
            }
            #pragma unroll
            for (int k = 0; k < 4; k++) {
                const uint32_t off = SWZ((uint32_t)((brb + 16 * k) * 128 + bc * 16));
                *(uint4*)(Bh + off) = pBh[k];
                *(uint4*)(Bl + off) = pBl[k];
            }
            BAR_ARRIVE(1 + s);             // stage s full

            // prefetch next chunk (overlaps consumer mma + our empty-wait)
            if (c + 1 < NCH) {
                const int jn = j0 + JC;
                #pragma unroll
                for (int i = 0; i < 4; i++)
                    pa[i] = __ldcs((const float4*)(adj + (long)(grow0 + rbase + 8 * i) * NN + jn) + f4);
                #pragma unroll
                for (int k = 0; k < 4; k++) {
                    pBh[k] = *(const uint4*)(hTh[k] + (long)(jn + bc * 8) * 2);
                    pBl[k] = *(const uint4*)(hTl[k] + (long)(jn + bc * 8) * 2);
                }
            }
        }
    } else {
        // ==================== CONSUMER (4 warps) ====================
        const int wc = (t - 128) >> 5;     // 0..3
        const int npair = wc;              // cols npair*16 .. +15
        // tiles at m-rows 0 and 16

        float C0[2][4], C1[2][4];
        #pragma unroll
        for (int i = 0; i < 2; i++)
            #pragma unroll
            for (int q = 0; q < 4; q++) { C0[i][q] = 0.0f; C1[i][q] = 0.0f; }

        for (int c = 0; c < NCH; c++) {
            const int s = c & 1;
            BAR_SYNC(1 + s);               // wait stage s full

            const uint32_t tAh = tiles_u32 + s * STG;
            const uint32_t tAl = tAh + 4096;
            const uint32_t tBh = tAh + 8192;
            const uint32_t tBl = tAh + 16384;

            #pragma unroll
            for (int ks = 0; ks < 4; ks++) {
                uint32_t bh0, bh1, bh2, bh3, bl0, bl1, bl2, bl3;
                const uint32_t boff = SWZ((uint32_t)(
                    (npair * 16 + (lane & 7) + ((lane >> 4) << 3)) * 128 +
                    ks * 32 + (((lane >> 3) & 1) << 4)));
                LDSM4(bh0, bh1, bh2, bh3, tBh + boff);
                LDSM4(bl0, bl1, bl2, bl3, tBl + boff);

                uint32_t ah0, ah1, ah2, ah3, al0, al1, al2, al3;
                const uint32_t aoff0 = SWZ((uint32_t)(((lane & 15)) * 128 +
                                                      ks * 32 + ((lane >> 4) << 4)));
                LDSM4(ah0, ah1, ah2, ah3, tAh + aoff0);
                LDSM4(al0, al1, al2, al3, tAl + aoff0);
                MMA16816(C0[0], ah0, ah1, ah2, ah3, bh0, bh1);
                MMA16816(C0[0], ah0, ah1, ah2, ah3, bl0, bl1);
                MMA16816(C0[0], al0, al1, al2, al3, bh0, bh1);
                MMA16816(C0[1], ah0, ah1, ah2, ah3, bh2, bh3);
                MMA16816(C0[1], ah0, ah1, ah2, ah3, bl2, bl3);
                MMA16816(C0[1], al0, al1, al2, al3, bh2, bh3);

                const uint32_t aoff1 = SWZ((uint32_t)((16 + (lane & 15)) * 128 +
                                                      ks * 32 + ((lane >> 4) << 4)));
                LDSM4(ah0, ah1, ah2, ah3, tAh + aoff1);
                LDSM4(al0, al1, al2, al3, tAl + aoff1);
                MMA16816(C1[0], ah0, ah1, ah2, ah3, bh0, bh1);
                MMA16816(C1[0], ah0, ah1, ah2, ah3, bl0, bl1);
                MMA16816(C1[0], al0, al1, al2, al3, bh0, bh1);
                MMA16816(C1[1], ah0, ah1, ah2, ah3, bh2, bh3);
                MMA16816(C1[1], ah0, ah1, ah2, ah3, bl2, bl3);
                MMA16816(C1[1], al0, al1, al2, al3, bh2, bh3);
            }

            if (c + 2 < NCH) BAR_ARRIVE(3 + s);   // stage s empty
        }

        // epilogue: two 16x16 tiles per warp (m-rows 0 and 16)
        #pragma unroll
        for (int tile = 0; tile < 2; tile++) {
            const int mr = 16 * tile;
            const int r0 = grow0 + mr + (lane >> 2);
            #pragma unroll
            for (int lq = 0; lq < 2; lq++) {
                const int col = (npair * 2 + lq) * 8 + (lane & 3) * 2;
                const float (*C)[4] = tile ? C1 : C0;
                float2 lo; lo.x = C[lq][0]; lo.y = C[lq][1];
                float2 hi; hi.x = C[lq][2]; hi.y = C[lq][3];
                *(float2*)(out_h + (long)r0 * CC + col) = lo;
                *(float2*)(out_h + (long)(r0 + 8) * CC + col) = hi;
            }
        }
    }
}

// ===========================================================================
extern "C" void kernel_launch(void* const* d_in, const int* in_sizes, int n_in,
                              void* d_out, int out_size)
{
    const float* x   = (const float*)d_in[0];
    const float* adj = (const float*)d_in[1];
    const float* W1  = (const float*)d_in[2];
    const float* b1  = (const float*)d_in[3];
    const float* W2  = (const float*)d_in[4];
    const float* b2  = (const float*)d_in[5];
    const float* Wa  = (const float*)d_in[6];
    const float* ba  = (const float*)d_in[7];

    float* out_h = (float*)d_out;
    float* out_a = (float*)d_out + HOUT_ELEMS;

    const int k1_smem = (8192 + 4096 + 128 + 4096 + 2048) * 4;  // 74240 B
    cudaFuncSetAttribute(k1_mlp, cudaFuncAttributeMaxDynamicSharedMemorySize, k1_smem);
    const int kb_smem = 2 * STG + 1024;                          // 50176 B
    cudaFuncSetAttribute(kB_fused, cudaFuncAttributeMaxDynamicSharedMemorySize, kb_smem);

    k1_mlp<<<TOTROWS / 32, 256, k1_smem>>>(x, W1, b1, W2, b2, Wa);
    kA_rowsum<<<TOTROWS / 4, 256>>>(adj, ba);
    kB_fused<<<TOTROWS / MB, 256, kb_smem>>>(adj, ba, out_h, out_a);
}

// round 14
// speedup vs baseline: 1.1531x; 1.1531x over previous
#include <cuda_runtime.h>
#include <cuda_fp16.h>
#include <cstdint>

#define BATCH 2
#define NN    4096
#define CINN  128
#define CC    64
#define TOTROWS (BATCH * NN)       // 8192
#define HOUT_ELEMS (TOTROWS * CC)  // 524288

// ---------------- scratch (device globals; no allocation allowed) ----------
__device__ float g_u[TOTROWS];
__device__ float g_v[TOTROWS];
__device__ float g_invS[TOTROWS];
__device__ __half g_hT16[BATCH * CC * NN];  // [b][c][n] fp16 h^T

__device__ __forceinline__ float sigmoidf(float x) {
    return __fdividef(1.0f, 1.0f + __expf(-x));
}
__device__ __forceinline__ uint32_t smem_u32(const void* p) {
    uint32_t a;
    asm("{ .reg .u64 t; cvta.to.shared.u64 t, %1; cvt.u32.u64 %0, t; }" : "=r"(a) : "l"(p));
    return a;
}
#define SWZ(x) ((x) ^ (((x) >> 3) & 0x70))

#define BAR_SYNC(id)   asm volatile("bar.sync %0, 512;"   :: "r"(id) : "memory")
#define BAR_ARRIVE(id) asm volatile("bar.arrive %0, 512;" :: "r"(id) : "memory")

__device__ __forceinline__ uint32_t pack_h2(float a, float b) {
    __half2 h = __floats2half2_rn(a, b);
    return *(uint32_t*)&h;
}

#define LDSM4(r0, r1, r2, r3, addr)                                            \
    asm volatile("ldmatrix.sync.aligned.m8n8.x4.shared.b16 {%0,%1,%2,%3}, [%4];" \
                 : "=r"(r0), "=r"(r1), "=r"(r2), "=r"(r3) : "r"(addr))

#define MMA16816(c, a0, a1, a2, a3, b0, b1)                                    \
    asm volatile("mma.sync.aligned.m16n8k16.row.col.f32.f16.f16.f32 "          \
                 "{%0,%1,%2,%3}, {%4,%5,%6,%7}, {%8,%9}, {%0,%1,%2,%3};"       \
                 : "+f"((c)[0]), "+f"((c)[1]), "+f"((c)[2]), "+f"((c)[3])      \
                 : "r"(a0), "r"(a1), "r"(a2), "r"(a3), "r"(b0), "r"(b1))

// ===========================================================================
// Kernel 1: h = relu(relu(x@W1+b1)@W2+b2); u, v; h^T -> fp16
// ===========================================================================
extern __shared__ float s1[];

__global__ void k1_mlp(const float* __restrict__ x,
                       const float* __restrict__ W1,
                       const float* __restrict__ b1,
                       const float* __restrict__ W2,
                       const float* __restrict__ b2,
                       const float* __restrict__ Wa)
{
    float* sW1 = s1;             // 8192
    float* sW2 = sW1 + 8192;     // 4096
    float* sWa = sW2 + 4096;     // 128
    float* sX  = sWa + 128;      // 4096 (reused as sH2)
    float* sH1 = sX + 4096;      // 2048

    const int t = threadIdx.x;
    const int grow0 = blockIdx.x * 32;

    {
        const float4* W1v = (const float4*)W1;
        float4* d = (float4*)sW1;
        #pragma unroll
        for (int p = t; p < 2048; p += 256) d[p] = W1v[p];
        const float4* W2v = (const float4*)W2;
        float4* d2 = (float4*)sW2;
        #pragma unroll
        for (int p = t; p < 1024; p += 256) d2[p] = W2v[p];
        if (t < 32) ((float4*)sWa)[t] = ((const float4*)Wa)[t];
        const float4* Xv = (const float4*)(x + (long)grow0 * CINN);
        float4* dx = (float4*)sX;
        #pragma unroll
        for (int p = t; p < 1024; p += 256) dx[p] = Xv[p];
    }
    __syncthreads();

    const int ch = t & 63;
    const int rg = t >> 6;
    const float bb1 = b1[ch];
    const float bb2 = b2[ch];

    float acc[8];
    #pragma unroll
    for (int k = 0; k < 8; k++) acc[k] = bb1;

    #pragma unroll 4
    for (int i = 0; i < CINN; i += 4) {
        float w0 = sW1[(i + 0) * 64 + ch];
        float w1 = sW1[(i + 1) * 64 + ch];
        float w2 = sW1[(i + 2) * 64 + ch];
        float w3 = sW1[(i + 3) * 64 + ch];
        #pragma unroll
        for (int k = 0; k < 8; k++) {
            const float4 x4 = *(const float4*)(sX + (rg + 4 * k) * CINN + i);
            acc[k] = fmaf(x4.x, w0, acc[k]);
            acc[k] = fmaf(x4.y, w1, acc[k]);
            acc[k] = fmaf(x4.z, w2, acc[k]);
            acc[k] = fmaf(x4.w, w3, acc[k]);
        }
    }
    #pragma unroll
    for (int k = 0; k < 8; k++)
        sH1[(rg + 4 * k) * 64 + ch] = fmaxf(acc[k], 0.0f);
    __syncthreads();

    #pragma unroll
    for (int k = 0; k < 8; k++) acc[k] = bb2;

    #pragma unroll 4
    for (int i = 0; i < CC; i += 4) {
        float w0 = sW2[(i + 0) * 64 + ch];
        float w1 = sW2[(i + 1) * 64 + ch];
        float w2 = sW2[(i + 2) * 64 + ch];
        float w3 = sW2[(i + 3) * 64 + ch];
        #pragma unroll
        for (int k = 0; k < 8; k++) {
            const float4 h4 = *(const float4*)(sH1 + (rg + 4 * k) * 64 + i);
            acc[k] = fmaf(h4.x, w0, acc[k]);
            acc[k] = fmaf(h4.y, w1, acc[k]);
            acc[k] = fmaf(h4.z, w2, acc[k]);
            acc[k] = fmaf(h4.w, w3, acc[k]);
        }
    }

    float* sH2 = sX;
    #pragma unroll
    for (int k = 0; k < 8; k++) {
        const int r = rg + 4 * k;
        sH2[r * 64 + ch] = fmaxf(acc[k], 0.0f);
    }
    __syncthreads();

    // h^T fp16: thread t -> channel t>>2, nodes (t&3)*8 .. +7
    {
        const int b = grow0 >> 12;
        const int nloc0 = (grow0 & (NN - 1));   // batch-local node base
        const int ch2 = t >> 2;
        const int n0 = (t & 3) * 8;
        uint32_t hp[4];
        #pragma unroll
        for (int q = 0; q < 4; q++) {
            const float e0 = sH2[(n0 + 2 * q + 0) * 64 + ch2];
            const float e1 = sH2[(n0 + 2 * q + 1) * 64 + ch2];
            hp[q] = pack_h2(e0, e1);
        }
        const long gi = (long)(b * CC + ch2) * NN + nloc0 + n0;
        *(uint4*)((char*)g_hT16 + gi * 2) = *(uint4*)hp;
    }

    const int w = t >> 5, lane = t & 31;
    for (int rr = w * 4; rr < w * 4 + 4; rr++) {
        const float a0 = sH2[rr * 64 + lane];
        const float a1 = sH2[rr * 64 + lane + 32];
        float up = a0 * sWa[lane]      + a1 * sWa[lane + 32];
        float vp = a0 * sWa[64 + lane] + a1 * sWa[96 + lane];
        #pragma unroll
        for (int off = 16; off > 0; off >>= 1) {
            up += __shfl_down_sync(0xffffffffu, up, off);
            vp += __shfl_down_sync(0xffffffffu, vp, off);
        }
        if (lane == 0) { g_u[grow0 + rr] = up; g_v[grow0 + rr] = vp; }
    }
}

// ===========================================================================
// Kernel A: row sums only -> g_invS
// ===========================================================================
__global__ void kA_rowsum(const float* __restrict__ adj,
                          const float* __restrict__ ba)
{
    __shared__ __align__(16) float sV[NN];
    __shared__ float sRed[8];

    const int t = threadIdx.x;
    const int grow0 = blockIdx.x * 4;
    const int b = grow0 >> 12;

    {
        const float4* vv = (const float4*)(g_v + (long)b * NN);
        float4* d = (float4*)sV;
        #pragma unroll
        for (int p = t; p < 1024; p += 256) d[p] = vv[p];
    }
    __syncthreads();

    const int rg = t >> 6, l64 = t & 63;
    const int grow = grow0 + rg;
    const float u = g_u[grow] + ba[0];
    const float4* ar = (const float4*)(adj + (long)grow * NN);

    float s = 0.0f;
    #pragma unroll 4
    for (int it = 0; it < 16; it++) {
        const int f = l64 + 64 * it;
        const float4 a4 = __ldcs(ar + f);
        const int j = f * 4;
        s += a4.x * sigmoidf(u + sV[j + 0]);
        s += a4.y * sigmoidf(u + sV[j + 1]);
        s += a4.z * sigmoidf(u + sV[j + 2]);
        s += a4.w * sigmoidf(u + sV[j + 3]);
    }
    #pragma unroll
    for (int off = 16; off > 0; off >>= 1)
        s += __shfl_down_sync(0xffffffffu, s, off);
    const int w = t >> 5, lane = t & 31;
    if (lane == 0) sRed[w] = s;
    __syncthreads();
    if (t < 4) {
        const float S = sRed[2 * t] + sRed[2 * t + 1];
        g_invS[grow0 + t] = 1.0f / (S + 1e-10f);
    }
}

// ===========================================================================
// Kernel B (warp-specialized, fp16): MB=64 rows/CTA, grid 128, 512 thr.
// Warps 0-7 = producers: LDG adj -> sigmoid/normalize -> STG a (fp32) +
// STS fp16 A/B tiles. Warps 8-15 = consumers: ldmatrix + mma.sync f16
// (2 output tiles each). Double-buffered, named barriers:
//   FULL(s) = 1+s, EMPTY(s) = 3+s.
// ===========================================================================
#define MB 64
#define JC 64
#define NCH (NN / JC)
#define STG 16384   // A 8K | B 8K

__global__ void __launch_bounds__(512, 1)
kB_fused(const float* __restrict__ adj,
         const float* __restrict__ ba,
         float* __restrict__ out_h,
         float* __restrict__ out_a)
{
    extern __shared__ char dsm[];
    __shared__ __align__(16) float sV[NN];

    char* tiles = (char*)(((uintptr_t)dsm + 1023) & ~(uintptr_t)1023);
    const uint32_t tiles_u32 = smem_u32(tiles);

    const int t = threadIdx.x;
    const int lane = t & 31;
    const int grow0 = blockIdx.x * MB;
    const int b = grow0 >> 12;

    {
        const float4* vv = (const float4*)(g_v + (long)b * NN);
        float4* d = (float4*)sV;
        #pragma unroll
        for (int p = t; p < 1024; p += 512) d[p] = vv[p];
    }
    __syncthreads();   // sV visible; ONLY use of barrier 0

    if (t < 256) {
        // ==================== PRODUCER ====================
        const float bav = ba[0];
        const int rbase = t >> 4;       // 0..15 -> rows rbase+16i (i=0..3)
        const int f4 = t & 15;
        float ru[4], rinv[4];
        #pragma unroll
        for (int i = 0; i < 4; i++) {
            ru[i]   = g_u[grow0 + rbase + 16 * i] + bav;
            rinv[i] = g_invS[grow0 + rbase + 16 * i];
        }
        // B staging: slots t and t+256; slot -> brow = slot>>3, bc = slot&7
        const int brow0 = t >> 3;
        const int brow1 = (t + 256) >> 3;
        const int bc = t & 7;
        const char* hTA = (const char*)(g_hT16 + (long)(b * CC + brow0) * NN);
        const char* hTB = (const char*)(g_hT16 + (long)(b * CC + brow1) * NN);

        float4 pa[4];
        uint4 pB0, pB1;

        // prologue: LDG chunk 0
        #pragma unroll
        for (int i = 0; i < 4; i++)
            pa[i] = __ldcs((const float4*)(adj + (long)(grow0 + rbase + 16 * i) * NN) + f4);
        pB0 = *(const uint4*)(hTA + (long)(bc * 8) * 2);
        pB1 = *(const uint4*)(hTB + (long)(bc * 8) * 2);

        for (int c = 0; c < NCH; c++) {
            const int j0 = c * JC;
            const int s = c & 1;
            char* Ah = tiles + s * STG;
            char* Bh = Ah + 8192;

            if (c >= 2) BAR_SYNC(3 + s);   // wait consumers freed stage s

            // compute e + commit
            const int jj = f4 * 4;
            #pragma unroll
            for (int i = 0; i < 4; i++) {
                const int row = rbase + 16 * i;
                const float u = ru[i], inv = rinv[i];
                const float4 a4 = pa[i];
                float4 o;
                o.x = a4.x * sigmoidf(u + sV[j0 + jj + 0]) * inv;
                o.y = a4.y * sigmoidf(u + sV[j0 + jj + 1]) * inv;
                o.z = a4.z * sigmoidf(u + sV[j0 + jj + 2]) * inv;
                o.w = a4.w * sigmoidf(u + sV[j0 + jj + 3]) * inv;
                __stcs((float4*)(out_a + (long)(grow0 + row) * NN + j0) + f4, o);
                uint2 hv;
                hv.x = pack_h2(o.x, o.y);
                hv.y = pack_h2(o.z, o.w);
                const uint32_t off = SWZ((uint32_t)(row * 128 + f4 * 8));
                *(uint2*)(Ah + off) = hv;
            }
            {
                const uint32_t off0 = SWZ((uint32_t)(brow0 * 128 + bc * 16));
                const uint32_t off1 = SWZ((uint32_t)(brow1 * 128 + bc * 16));
                *(uint4*)(Bh + off0) = pB0;
                *(uint4*)(Bh + off1) = pB1;
            }
            BAR_ARRIVE(1 + s);             // stage s full

            // prefetch next chunk (overlaps consumer mma + our empty-wait)
            if (c + 1 < NCH) {
                const int jn = j0 + JC;
                #pragma unroll
                for (int i = 0; i < 4; i++)
                    pa[i] = __ldcs((const float4*)(adj + (long)(grow0 + rbase + 16 * i) * NN + jn) + f4);
                pB0 = *(const uint4*)(hTA + (long)(jn + bc * 8) * 2);
                pB1 = *(const uint4*)(hTB + (long)(jn + bc * 8) * 2);
            }
        }
    } else {
        // ==================== CONSUMER ====================
        const int wc = (t - 256) >> 5;     // 0..7
        const int npair = wc >> 1;         // 0..3
        const int mrow0 = (wc & 1) * 16;   // tiles at mrow0 and mrow0+32

        float C0[2][4], C1[2][4];
        #pragma unroll
        for (int i = 0; i < 2; i++)
            #pragma unroll
            for (int q = 0; q < 4; q++) { C0[i][q] = 0.0f; C1[i][q] = 0.0f; }

        for (int c = 0; c < NCH; c++) {
            const int s = c & 1;
            BAR_SYNC(1 + s);               // wait stage s full

            const uint32_t tA = tiles_u32 + s * STG;
            const uint32_t tB = tA + 8192;

            #pragma unroll
            for (int ks = 0; ks < 4; ks++) {
                uint32_t b0, b1, b2, b3;
                const uint32_t boff = SWZ((uint32_t)(
                    (npair * 16 + (lane & 7) + ((lane >> 4) << 3)) * 128 +
                    ks * 32 + (((lane >> 3) & 1) << 4)));
                LDSM4(b0, b1, b2, b3, tB + boff);

                uint32_t a0, a1, a2, a3;
                const uint32_t aoff0 = SWZ((uint32_t)((mrow0 + (lane & 15)) * 128 +
                                                      ks * 32 + ((lane >> 4) << 4)));
                LDSM4(a0, a1, a2, a3, tA + aoff0);
                MMA16816(C0[0], a0, a1, a2, a3, b0, b1);
                MMA16816(C0[1], a0, a1, a2, a3, b2, b3);

                const uint32_t aoff1 = SWZ((uint32_t)((mrow0 + 32 + (lane & 15)) * 128 +
                                                      ks * 32 + ((lane >> 4) << 4)));
                LDSM4(a0, a1, a2, a3, tA + aoff1);
                MMA16816(C1[0], a0, a1, a2, a3, b0, b1);
                MMA16816(C1[1], a0, a1, a2, a3, b2, b3);
            }

            if (c + 2 < NCH) BAR_ARRIVE(3 + s);   // stage s empty
        }

        // epilogue: two 16x16 tiles per warp
        #pragma unroll
        for (int tile = 0; tile < 2; tile++) {
            const int mr = mrow0 + 32 * tile;
            const int r0 = grow0 + mr + (lane >> 2);
            #pragma unroll
            for (int lq = 0; lq < 2; lq++) {
                const int col = (npair * 2 + lq) * 8 + (lane & 3) * 2;
                const float (*C)[4] = tile ? C1 : C0;
                float2 lo; lo.x = C[lq][0]; lo.y = C[lq][1];
                float2 hi; hi.x = C[lq][2]; hi.y = C[lq][3];
                *(float2*)(out_h + (long)r0 * CC + col) = lo;
                *(float2*)(out_h + (long)(r0 + 8) * CC + col) = hi;
            }
        }
    }
}

// ===========================================================================
extern "C" void kernel_launch(void* const* d_in, const int* in_sizes, int n_in,
                              void* d_out, int out_size)
{
    const float* x   = (const float*)d_in[0];
    const float* adj = (const float*)d_in[1];
    const float* W1  = (const float*)d_in[2];
    const float* b1  = (const float*)d_in[3];
    const float* W2  = (const float*)d_in[4];
    const float* b2  = (const float*)d_in[5];
    const float* Wa  = (const float*)d_in[6];
    const float* ba  = (const float*)d_in[7];

    float* out_h = (float*)d_out;
    float* out_a = (float*)d_out + HOUT_ELEMS;

    const int k1_smem = (8192 + 4096 + 128 + 4096 + 2048) * 4;  // 74240 B
    cudaFuncSetAttribute(k1_mlp, cudaFuncAttributeMaxDynamicSharedMemorySize, k1_smem);
    const int kb_smem = 2 * STG + 1024;                          // 33792 B
    cudaFuncSetAttribute(kB_fused, cudaFuncAttributeMaxDynamicSharedMemorySize, kb_smem);

    k1_mlp<<<TOTROWS / 32, 256, k1_smem>>>(x, W1, b1, W2, b2, Wa);
    kA_rowsum<<<TOTROWS / 4, 256>>>(adj, ba);
    kB_fused<<<TOTROWS / MB, 512, kb_smem>>>(adj, ba, out_h, out_a);
}